// round 2
// baseline (speedup 1.0000x reference)
#include <cuda_runtime.h>

#define MAXN 100000
#define MAXG 512

// ---------------- scratch (device globals; no allocation allowed) ----------
__device__ __align__(16) float g_denom1[MAXN * 8];
__device__ __align__(16) float g_num1[MAXN * 8];
__device__ __align__(16) float g_acc2[MAXN * 8];
__device__ __align__(16) float g_denom2[MAXN];
__device__ __align__(16) float g_h2[MAXN * 8];
__device__ float g_as2[MAXN];
__device__ float g_ad2[MAXN];
__device__ __align__(16) float g_gsum[MAXG * 8];
__device__ float g_gcnt[MAXG];
__device__ float g_s1[8];
__device__ float g_d1[8];

// ---------------- helpers ----------------
__device__ __forceinline__ float lrelu(float z) { return z > 0.f ? z : 0.2f * z; }

// ---------------- zero scratch ----------------
__global__ void zero_all(int N, int G) {
    int stride = gridDim.x * blockDim.x;
    int i = blockIdx.x * blockDim.x + threadIdx.x;
    int n8 = N * 8;
    for (int k = i; k < n8; k += stride) {
        g_denom1[k] = 0.f;
        g_num1[k] = 0.f;
        g_acc2[k] = 0.f;
    }
    for (int k = i; k < N; k += stride) g_denom2[k] = 0.f;
    if (i < G * 8) g_gsum[i] = 0.f;
    if (i < G) g_gcnt[i] = 0.f;
}

// ---------------- precompute s1[h] = sum_c W1[0,h*8+c]*att_src1[h,c] -------
__global__ void precomp(const float* __restrict__ W1,
                        const float* __restrict__ as1,
                        const float* __restrict__ ad1) {
    int h = threadIdx.x;
    if (h >= 8) return;
    float s = 0.f, d = 0.f;
#pragma unroll
    for (int c = 0; c < 8; c++) {
        float w = W1[h * 8 + c];
        s += w * as1[h * 8 + c];
        d += w * ad1[h * 8 + c];
    }
    g_s1[h] = s;
    g_d1[h] = d;
}

// ---------------- layer 1 edge pass ----------------
// per edge: w_h = exp(lrelu(x_s*s1[h] + x_d*d1[h]));
// denom1[d,h] += w_h;  num1[d,h] += w_h * x_s
__global__ void edge1(const int* __restrict__ ei, const float* __restrict__ x, int E) {
    int i = blockIdx.x * blockDim.x + threadIdx.x;
    if (i >= E) return;
    int s = ei[i];
    int d = ei[E + i];
    float xs = __ldg(x + s);
    float xd = __ldg(x + d);
    float w[8];
#pragma unroll
    for (int h = 0; h < 8; h++) {
        float z = lrelu(xs * g_s1[h] + xd * g_d1[h]);
        w[h] = __expf(z);
    }
    float4* D = (float4*)&g_denom1[d * 8];
    atomicAdd(D, make_float4(w[0], w[1], w[2], w[3]));
    atomicAdd(D + 1, make_float4(w[4], w[5], w[6], w[7]));
    float4* Nu = (float4*)&g_num1[d * 8];
    atomicAdd(Nu, make_float4(w[0] * xs, w[1] * xs, w[2] * xs, w[3] * xs));
    atomicAdd(Nu + 1, make_float4(w[4] * xs, w[5] * xs, w[6] * xs, w[7] * xs));
}

// ---------------- layer 1 finalize + layer 2 node prep ----------------
// t[h] = (num + w_self*x)/(den + w_self + eps)
// feat[k] = elu(t[k/8]*W1[k] + b1[k])   (k = 0..63)   [never stored]
// h2[c]   = sum_k feat[k]*W2[k,c];  as2/ad2 = h2 . att2
__global__ void node1(const float* __restrict__ x,
                      const float* __restrict__ W1, const float* __restrict__ b1,
                      const float* __restrict__ W2,
                      const float* __restrict__ as2w, const float* __restrict__ ad2w,
                      int N) {
    __shared__ float sW1[64], sb1[64], sW2[512], sas[8], sad[8], ss1[8], sd1[8];
    int t = threadIdx.x;
    if (t < 64) { sW1[t] = W1[t]; sb1[t] = b1[t]; }
    for (int k = t; k < 512; k += blockDim.x) sW2[k] = W2[k];
    if (t < 8) { sas[t] = as2w[t]; sad[t] = ad2w[t]; ss1[t] = g_s1[t]; sd1[t] = g_d1[t]; }
    __syncthreads();

    int n = blockIdx.x * blockDim.x + t;
    if (n >= N) return;
    float xn = __ldg(x + n);
    float tv[8];
#pragma unroll
    for (int h = 0; h < 8; h++) {
        float z = lrelu(xn * (ss1[h] + sd1[h]));  // self-loop attention logit
        float w = __expf(z);
        float den = g_denom1[n * 8 + h] + w;
        float num = g_num1[n * 8 + h] + w * xn;
        tv[h] = num / (den + 1e-16f);
    }
    float acc[8];
#pragma unroll
    for (int c = 0; c < 8; c++) acc[c] = 0.f;
#pragma unroll
    for (int k = 0; k < 64; k++) {
        float v = tv[k >> 3] * sW1[k] + sb1[k];
        v = v > 0.f ? v : expm1f(v);  // ELU
#pragma unroll
        for (int c = 0; c < 8; c++) acc[c] += v * sW2[k * 8 + c];
    }
    float as = 0.f, ad = 0.f;
#pragma unroll
    for (int c = 0; c < 8; c++) {
        g_h2[n * 8 + c] = acc[c];
        as += acc[c] * sas[c];
        ad += acc[c] * sad[c];
    }
    g_as2[n] = as;
    g_ad2[n] = ad;
}

// ---------------- layer 2 edge pass ----------------
__global__ void edge2(const int* __restrict__ ei, int E) {
    int i = blockIdx.x * blockDim.x + threadIdx.x;
    if (i >= E) return;
    int s = ei[i];
    int d = ei[E + i];
    float e = lrelu(__ldg(g_as2 + s) + __ldg(g_ad2 + d));
    float w = __expf(e);
    float4 h0 = __ldg((const float4*)&g_h2[s * 8]);
    float4 h1 = __ldg((const float4*)&g_h2[s * 8 + 4]);
    float4* A = (float4*)&g_acc2[d * 8];
    atomicAdd(A, make_float4(w * h0.x, w * h0.y, w * h0.z, w * h0.w));
    atomicAdd(A + 1, make_float4(w * h1.x, w * h1.y, w * h1.z, w * h1.w));
    atomicAdd(&g_denom2[d], w);
}

// ---------------- layer 2 finalize + graph pooling accumulate -------------
__global__ void node2(const int* __restrict__ batch, const float* __restrict__ b2, int N) {
    int n = blockIdx.x * blockDim.x + threadIdx.x;
    if (n >= N) return;
    float e = lrelu(g_as2[n] + g_ad2[n]);
    float w = __expf(e);
    float inv = 1.f / (g_denom2[n] + w + 1e-16f);
    int b = batch[n];
    float o[8];
#pragma unroll
    for (int c = 0; c < 8; c++)
        o[c] = (g_acc2[n * 8 + c] + w * g_h2[n * 8 + c]) * inv + b2[c];
    atomicAdd((float4*)&g_gsum[b * 8], make_float4(o[0], o[1], o[2], o[3]));
    atomicAdd((float4*)&g_gsum[b * 8 + 4], make_float4(o[4], o[5], o[6], o[7]));
    atomicAdd(&g_gcnt[b], 1.f);
}

// ---------------- pooled -> linear -> log_softmax ----------------
__global__ void final_k(const float* __restrict__ lw, const float* __restrict__ lb,
                        float* __restrict__ out, int G) {
    int g = blockIdx.x * blockDim.x + threadIdx.x;
    if (g >= G) return;
    float inv = 1.f / fmaxf(g_gcnt[g], 1.f);
    float p[8];
#pragma unroll
    for (int c = 0; c < 8; c++) p[c] = g_gsum[g * 8 + c] * inv;
    float l[10];
    float m = -1e30f;
#pragma unroll
    for (int o = 0; o < 10; o++) {
        float a = lb[o];
#pragma unroll
        for (int c = 0; c < 8; c++) a += p[c] * lw[c * 10 + o];
        l[o] = a;
        m = fmaxf(m, a);
    }
    float s = 0.f;
#pragma unroll
    for (int o = 0; o < 10; o++) s += expf(l[o] - m);
    float lse = m + logf(s);
#pragma unroll
    for (int o = 0; o < 10; o++) out[g * 10 + o] = l[o] - lse;
}

// ---------------- launch ----------------
extern "C" void kernel_launch(void* const* d_in, const int* in_sizes, int n_in,
                              void* d_out, int out_size) {
    const float* x   = (const float*)d_in[0];
    const int*   ei  = (const int*)d_in[1];
    const int*   bat = (const int*)d_in[2];
    // d_in[3] = num_graphs (scalar); G derived from out_size instead
    const float* W1  = (const float*)d_in[4];
    const float* as1 = (const float*)d_in[5];
    const float* ad1 = (const float*)d_in[6];
    const float* b1  = (const float*)d_in[7];
    const float* W2  = (const float*)d_in[8];
    const float* as2 = (const float*)d_in[9];
    const float* ad2 = (const float*)d_in[10];
    const float* b2  = (const float*)d_in[11];
    const float* lw  = (const float*)d_in[12];
    const float* lb  = (const float*)d_in[13];

    int N = in_sizes[0];       // x has N*1 elements
    int E = in_sizes[1] / 2;   // edge_index [2,E]
    int G = out_size / 10;
    float* out = (float*)d_out;

    zero_all<<<(N * 8 + 255) / 256, 256>>>(N, G);
    precomp<<<1, 8>>>(W1, as1, ad1);
    edge1<<<(E + 255) / 256, 256>>>(ei, x, E);
    node1<<<(N + 127) / 128, 128>>>(x, W1, b1, W2, as2, ad2, N);
    edge2<<<(E + 255) / 256, 256>>>(ei, E);
    node2<<<(N + 255) / 256, 256>>>(bat, b2, N);
    final_k<<<(G + 127) / 128, 128>>>(lw, lb, out, G);
}